// round 9
// baseline (speedup 1.0000x reference)
#include <cuda_runtime.h>

#define Hh 4
#define Oo 32
#define Mm 128
#define M2 256
#define Dd 16
#define Bb 1024
#define HO 128
#define HOB (HO*Bb)
#define JIT 1e-4f
#define LDA 129
#define LDT 132

// ---------------- f32x2 helpers ----------------
__device__ __forceinline__ unsigned long long pk2(float lo, float hi) {
    unsigned long long r;
    asm("mov.b64 %0, {%1, %2};" : "=l"(r) : "f"(lo), "f"(hi));
    return r;
}
__device__ __forceinline__ float2 upk2(unsigned long long v) {
    float2 r;
    asm("mov.b64 {%0, %1}, %2;" : "=f"(r.x), "=f"(r.y) : "l"(v));
    return r;
}
__device__ __forceinline__ unsigned long long ffma2(unsigned long long a, unsigned long long b, unsigned long long c) {
    unsigned long long d;
    asm("fma.rn.f32x2 %0, %1, %2, %3;" : "=l"(d) : "l"(a), "l"(b), "l"(c));
    return d;
}

// ---------------- device scratch ----------------
__device__ float g_sf2[Hh];
__device__ float g_invls[Hh][Dd];
__device__ float g_Xs[Hh][Bb][Dd];
__device__ float g_xn[Hh][Bb];
__device__ float g_Zs[HO][M2][Dd];
__device__ float g_zn[HO][M2];
__device__ float g_kuu2[HO][M2][M2];
__device__ float g_cov[HO][M2][M2];
__device__ float g_Wt[HO][M2][M2];     // Wt[k][i] = Linv256[i][k]
__device__ float g_R[HO][M2][M2];
__device__ float g_vm[HO][M2];
__device__ float g_mj[HO][M2];
__device__ float g_kx[HO][M2][Bb];
__device__ float g_a[HO][M2][Bb];
__device__ float g_X1[HO][Mm][Mm];
__device__ float g_W11[HO][Mm][Mm];
__device__ float g_schur[HO][Mm][Mm];
__device__ float g_L11p[HO][Mm][Mm];
__device__ float g_L21p[HO][Mm][Mm];
__device__ float g_L22p[HO][Mm][Mm];
__device__ float g_d1p[2][HO][Bb];
__device__ float g_d2p[2][HO][Bb];
__device__ float g_mup[2][HO][Bb];

// ---------------- serial building blocks (dense 128, LD=129, blockDim-agnostic) ----------------
__device__ void chol128(float* Ls, float* dinv, int t) {
    for (int j = 0; j < Mm; j++) {
        if (t < 32) {
            float s = 0.0f;
            for (int k = t; k < j; k += 32) { float v = Ls[j * LDA + k]; s += v * v; }
            for (int w = 16; w; w >>= 1) s += __shfl_down_sync(0xffffffffu, s, w);
            if (t == 0) {
                float d = sqrtf(Ls[j * LDA + j] - s);
                Ls[j * LDA + j] = d;
                dinv[j] = 1.0f / d;
            }
        }
        __syncthreads();
        int i = j + 1 + t;
        if (i < Mm) {
            float s0 = 0, s1 = 0, s2 = 0, s3 = 0;
            int k = 0;
            for (; k + 3 < j; k += 4) {
                s0 += Ls[i * LDA + k]     * Ls[j * LDA + k];
                s1 += Ls[i * LDA + k + 1] * Ls[j * LDA + k + 1];
                s2 += Ls[i * LDA + k + 2] * Ls[j * LDA + k + 2];
                s3 += Ls[i * LDA + k + 3] * Ls[j * LDA + k + 3];
            }
            for (; k < j; k++) s0 += Ls[i * LDA + k] * Ls[j * LDA + k];
            Ls[i * LDA + j] = (Ls[i * LDA + j] - ((s0 + s1) + (s2 + s3))) * dinv[j];
        }
        __syncthreads();
    }
}

__device__ void trtri128_blocked(float* Ls, float* dinv, int t) {
    if (t == 0) Ls[0] = dinv[0];
    if (t == 1) Ls[64 * LDA + 64] = dinv[64];
    __syncthreads();
    for (int i = 1; i < 64; i++) {
        float v = 0.0f;
        bool actA = (t < i);
        int u = t - 128;
        bool actB = (u >= 0 && u < i);
        if (actA) {
            float s0 = 0, s1 = 0, s2 = 0, s3 = 0;
            int k = t;
            for (; k + 3 < i; k += 4) {
                s0 += Ls[i * LDA + k]     * Ls[(k)     * LDA + t];
                s1 += Ls[i * LDA + k + 1] * Ls[(k + 1) * LDA + t];
                s2 += Ls[i * LDA + k + 2] * Ls[(k + 2) * LDA + t];
                s3 += Ls[i * LDA + k + 3] * Ls[(k + 3) * LDA + t];
            }
            for (; k < i; k++) s0 += Ls[i * LDA + k] * Ls[k * LDA + t];
            v = -dinv[i] * ((s0 + s1) + (s2 + s3));
        } else if (actB) {
            const int O = 64 * LDA + 64;
            float s0 = 0, s1 = 0, s2 = 0, s3 = 0;
            int k = u;
            for (; k + 3 < i; k += 4) {
                s0 += Ls[O + i * LDA + k]     * Ls[O + (k)     * LDA + u];
                s1 += Ls[O + i * LDA + k + 1] * Ls[O + (k + 1) * LDA + u];
                s2 += Ls[O + i * LDA + k + 2] * Ls[O + (k + 2) * LDA + u];
                s3 += Ls[O + i * LDA + k + 3] * Ls[O + (k + 3) * LDA + u];
            }
            for (; k < i; k++) s0 += Ls[O + i * LDA + k] * Ls[O + k * LDA + u];
            v = -dinv[64 + i] * ((s0 + s1) + (s2 + s3));
        }
        __syncthreads();
        if (actA) Ls[i * LDA + t] = v;
        if (actB) Ls[(64 + i) * LDA + 64 + u] = v;
        if (t == 0) Ls[i * LDA + i] = dinv[i];
        if (t == 1) Ls[(64 + i) * LDA + 64 + i] = dinv[64 + i];
        __syncthreads();
    }
    for (int e = t; e < 64 * 64; e += blockDim.x) {
        int r = e >> 6, c = e & 63;
        if (c > r) { Ls[r * LDA + c] = 0.0f; Ls[(64 + r) * LDA + 64 + c] = 0.0f; }
        Ls[r * LDA + 64 + c] = 0.0f;
    }
    __syncthreads();
    int tx = t & 15, ty = (t >> 4) & 15;
    bool act = (t < 256);
    float T[4][4];
#pragma unroll
    for (int m = 0; m < 4; m++)
#pragma unroll
        for (int n = 0; n < 4; n++) T[m][n] = 0.0f;
    if (act) {
        for (int k = 0; k < 64; k++) {
            float a[4], b[4];
#pragma unroll
            for (int m = 0; m < 4; m++) a[m] = Ls[(64 + ty + 16 * m) * LDA + k];
#pragma unroll
            for (int n = 0; n < 4; n++) b[n] = Ls[k * LDA + tx + 16 * n];
#pragma unroll
            for (int m = 0; m < 4; m++)
#pragma unroll
                for (int n = 0; n < 4; n++) T[m][n] += a[m] * b[n];
        }
    }
    __syncthreads();
    if (act) {
#pragma unroll
        for (int m = 0; m < 4; m++)
#pragma unroll
            for (int n = 0; n < 4; n++) Ls[(64 + ty + 16 * m) * LDA + tx + 16 * n] = T[m][n];
    }
    __syncthreads();
#pragma unroll
    for (int m = 0; m < 4; m++)
#pragma unroll
        for (int n = 0; n < 4; n++) T[m][n] = 0.0f;
    if (act) {
        for (int k = 0; k < 64; k++) {
            float a[4], b[4];
#pragma unroll
            for (int m = 0; m < 4; m++) a[m] = Ls[(64 + ty + 16 * m) * LDA + 64 + k];
#pragma unroll
            for (int n = 0; n < 4; n++) b[n] = Ls[(64 + k) * LDA + tx + 16 * n];
#pragma unroll
            for (int m = 0; m < 4; m++)
#pragma unroll
                for (int n = 0; n < 4; n++) T[m][n] -= a[m] * b[n];
        }
    }
    __syncthreads();
    if (act) {
#pragma unroll
        for (int m = 0; m < 4; m++)
#pragma unroll
            for (int n = 0; n < 4; n++) Ls[(64 + ty + 16 * m) * LDA + tx + 16 * n] = T[m][n];
    }
    __syncthreads();
}

// ---------------- prep ----------------
__global__ void k_prep_theta(const float* __restrict__ theta) {
    int t = threadIdx.x;
    if (t < Hh * (Dd + 1)) {
        int h = t / (Dd + 1), c = t % (Dd + 1);
        float v = theta[t];
        if (c == 0) g_sf2[h] = expf(v);
        else        g_invls[h][c - 1] = expf(-v);
    }
}

__global__ void k_prep_x(const float* __restrict__ x) {
    int g = blockIdx.x * blockDim.x + threadIdx.x;
    if (g >= Hh * Bb) return;
    int h = g / Bb, b = g % Bb;
    float s = 0.0f;
#pragma unroll
    for (int d = 0; d < Dd; d++) {
        float v = x[b * Dd + d] * g_invls[h][d];
        g_Xs[h][b][d] = v;
        s += v * v;
    }
    g_xn[h][b] = s;
}

__global__ void k_prep_z(const float* __restrict__ z, const float* __restrict__ z_old) {
    int p = blockIdx.x;
    int h = p / Oo, o = p % Oo;
    int i = threadIdx.x;
    const float* src = (i < Mm) ? &z_old[(o * Mm + i) * Dd] : &z[(o * Mm + (i - Mm)) * Dd];
    float s = 0.0f;
#pragma unroll
    for (int d = 0; d < Dd; d++) {
        float v = src[d] * g_invls[h][d];
        g_Zs[p][i][d] = v;
        s += v * v;
    }
    g_zn[p][i] = s;
}

__global__ void k_kuu2() {
    __shared__ float zn[M2];
    int p = blockIdx.y, rc = blockIdx.x, t = threadIdx.x;
    float myz[Dd];
#pragma unroll
    for (int d = 0; d < Dd; d++) myz[d] = g_Zs[p][t][d];
    zn[t] = g_zn[p][t];
    __syncthreads();
    float sf2 = g_sf2[p / Oo];
#pragma unroll 2
    for (int e = 0; e < 16; e++) {
        int row = rc * 16 + e;
        float dot = 0.0f;
#pragma unroll
        for (int d = 0; d < Dd; d++) dot += g_Zs[p][row][d] * myz[d];
        float d2 = fmaxf(zn[row] + zn[t] - 2.0f * dot, 0.0f);
        g_kuu2[p][row][t] = sf2 * __expf(-0.5f * d2);
    }
}

__global__ void k_kx() {
    __shared__ float zs[M2][Dd + 1];
    __shared__ float zn[M2];
    int p = blockIdx.y, b0 = blockIdx.x * 128, t = threadIdx.x;
    int h = p / Oo;
    for (int e = t; e < M2 * Dd; e += 256) {
        int i = e >> 4, d = e & 15;
        zs[i][d] = g_Zs[p][i][d];
    }
    zn[t] = g_zn[p][t];
    __syncthreads();
    int bl = t & 127, half = t >> 7;
    float xr[Dd];
#pragma unroll
    for (int d = 0; d < Dd; d++) xr[d] = g_Xs[h][b0 + bl][d];
    float xnn = g_xn[h][b0 + bl];
    float sf2 = g_sf2[h];
    for (int ii = 0; ii < 128; ii++) {
        int i = half * 128 + ii;
        float dot = 0.0f;
#pragma unroll
        for (int d = 0; d < Dd; d++) dot += zs[i][d] * xr[d];
        float d2 = fmaxf(zn[i] + xnn - 2.0f * dot, 0.0f);
        g_kx[p][i][b0 + bl] = sf2 * __expf(-0.5f * d2);
    }
}

// ---------------- stage A (512 threads, FFMA2 sections) ----------------
// smem: Ls 16512 | X1 16896 | X2 16896 | stg 2048 | dinv 128 | yv 128 | mbuf 128 = 52736 fl = 210944 B
__global__ __launch_bounds__(512, 1) void k_stageA(
        const float* __restrict__ m_old, const float* __restrict__ L_old,
        const float* __restrict__ u_mean, const float* __restrict__ u_tril_vec) {
    extern __shared__ float sm[];
    float* Ls   = sm;            // stride LDA=129; later aliased by G (stride 128)
    float* X1   = sm + 16512;    // stride 128 (solve result), then LDT=132 (L_old^T)
    float* X2   = sm + 33408;    // stride 128, then 132 (u_tril^T)
    float* stg  = sm + 50304;    // [16][128]
    float* dinv = sm + 52352;
    float* yv   = sm + 52480;
    float* mbuf = sm + 52608;
    float* G    = sm;            // alias of Ls, stride 128
    int p = blockIdx.x, o = p % Oo, t = threadIdx.x;
    int tx = t & 15, ty = t >> 4;      // tx<16, ty<32
    int r4 = ty * 4;                   // row base for 4-row microtiles

    for (int e = t; e < Mm * Mm; e += 512) {
        int i = e >> 7, j = e & 127;
        float v = g_kuu2[p][i][j];
        if (i == j) v += JIT;
        Ls[i * LDA + j] = v;
    }
    if (t < 128) mbuf[t] = m_old[o * Mm + t];
    __syncthreads();

    chol128(Ls, dinv, t);
    trtri128_blocked(Ls, dinv, t);   // Ls = W11 (upper zeros)

    for (int e = t; e < Mm * Mm; e += 512) {
        int i = e >> 7, k = e & 127;
        float v = Ls[i * LDA + k];
        g_W11[p][i][k] = v;
        g_Wt[p][k][i]  = v;
    }

    // X1 = W11 @ kuf   (packed FFMA2; b from staged rows)
    {
        unsigned long long acc[4][4];
#pragma unroll
        for (int m = 0; m < 4; m++)
#pragma unroll
            for (int n = 0; n < 4; n++) acc[m][n] = 0ULL;
        for (int kc = 0; kc < Mm; kc += 16) {
            for (int e = t; e < 2048; e += 512) {
                int kk = e >> 7, c = e & 127;
                stg[kk * 128 + c] = g_kuu2[p][kc + kk][Mm + c];
            }
            __syncthreads();
#pragma unroll
            for (int kk = 0; kk < 16; kk++) {
                float4 b0 = *(const float4*)&stg[kk * 128 + tx * 8];
                float4 b1 = *(const float4*)&stg[kk * 128 + tx * 8 + 4];
                unsigned long long bp[4] = { pk2(b0.x, b0.y), pk2(b0.z, b0.w), pk2(b1.x, b1.y), pk2(b1.z, b1.w) };
#pragma unroll
                for (int m = 0; m < 4; m++) {
                    float av = Ls[(r4 + m) * LDA + kc + kk];
                    unsigned long long ad = pk2(av, av);
#pragma unroll
                    for (int n = 0; n < 4; n++) acc[m][n] = ffma2(ad, bp[n], acc[m][n]);
                }
            }
            __syncthreads();
        }
#pragma unroll
        for (int m = 0; m < 4; m++)
#pragma unroll
            for (int n = 0; n < 4; n++) {
                float2 v = upk2(acc[m][n]);
                *(float2*)&X1[(r4 + m) * 128 + tx * 8 + 2 * n] = v;
                *(float2*)&g_X1[p][r4 + m][tx * 8 + 2 * n] = v;
            }
    }
    // X2 = W11 @ L_old
    {
        unsigned long long acc[4][4];
#pragma unroll
        for (int m = 0; m < 4; m++)
#pragma unroll
            for (int n = 0; n < 4; n++) acc[m][n] = 0ULL;
        for (int kc = 0; kc < Mm; kc += 16) {
            for (int e = t; e < 2048; e += 512) {
                int kk = e >> 7, c = e & 127;
                stg[kk * 128 + c] = L_old[(o * Mm + kc + kk) * Mm + c];
            }
            __syncthreads();
#pragma unroll
            for (int kk = 0; kk < 16; kk++) {
                float4 b0 = *(const float4*)&stg[kk * 128 + tx * 8];
                float4 b1 = *(const float4*)&stg[kk * 128 + tx * 8 + 4];
                unsigned long long bp[4] = { pk2(b0.x, b0.y), pk2(b0.z, b0.w), pk2(b1.x, b1.y), pk2(b1.z, b1.w) };
#pragma unroll
                for (int m = 0; m < 4; m++) {
                    float av = Ls[(r4 + m) * LDA + kc + kk];
                    unsigned long long ad = pk2(av, av);
#pragma unroll
                    for (int n = 0; n < 4; n++) acc[m][n] = ffma2(ad, bp[n], acc[m][n]);
                }
            }
            __syncthreads();
        }
#pragma unroll
        for (int m = 0; m < 4; m++)
#pragma unroll
            for (int n = 0; n < 4; n++) {
                float2 v = upk2(acc[m][n]);
                *(float2*)&X2[(r4 + m) * 128 + tx * 8 + 2 * n] = v;
            }
    }
    __syncthreads();

    // yv = W11 @ m_old
    if (t < 128) {
        float s = 0.0f;
        for (int k = 0; k <= t; k++) s += Ls[t * LDA + k] * mbuf[k];
        yv[t] = s;
        g_vm[p][t] = s;
    }
    __syncthreads();

    // m_joint
    if (t < 128) {
        float s = 0.0f;
        for (int i = 0; i < Mm; i++) s += X1[i * 128 + t] * yv[i];
        g_mj[p][t] = mbuf[t];
        g_mj[p][Mm + t] = s + u_mean[o * Mm + t];
    }
    __syncthreads();

    // G[r][c] = sum_i X2[i][r] * X1[i][c]  (overwrites Ls region, stride 128)
    {
        unsigned long long acc[4][4];
#pragma unroll
        for (int m = 0; m < 4; m++)
#pragma unroll
            for (int n = 0; n < 4; n++) acc[m][n] = 0ULL;
        for (int i = 0; i < Mm; i++) {
            float4 b0 = *(const float4*)&X1[i * 128 + tx * 8];
            float4 b1 = *(const float4*)&X1[i * 128 + tx * 8 + 4];
            unsigned long long bp[4] = { pk2(b0.x, b0.y), pk2(b0.z, b0.w), pk2(b1.x, b1.y), pk2(b1.z, b1.w) };
#pragma unroll
            for (int m = 0; m < 4; m++) {
                float av = X2[i * 128 + r4 + m];
                unsigned long long ad = pk2(av, av);
#pragma unroll
                for (int n = 0; n < 4; n++) acc[m][n] = ffma2(ad, bp[n], acc[m][n]);
            }
        }
        // schur = kuu_new + jit I - X1^T X1 (compute before writing G to keep regs tight is fine; independent)
        __syncthreads();
#pragma unroll
        for (int m = 0; m < 4; m++)
#pragma unroll
            for (int n = 0; n < 4; n++) {
                float2 v = upk2(acc[m][n]);
                *(float2*)&G[(r4 + m) * 128 + tx * 8 + 2 * n] = v;
            }
    }

    // schur[i][j] = kuu_new[i][j] + jit - sum_k X1[k][i] X1[k][j]
    {
        unsigned long long acc[4][4];
#pragma unroll
        for (int m = 0; m < 4; m++)
#pragma unroll
            for (int n = 0; n < 4; n++) acc[m][n] = 0ULL;
        for (int k = 0; k < Mm; k++) {
            float4 b0 = *(const float4*)&X1[k * 128 + tx * 8];
            float4 b1 = *(const float4*)&X1[k * 128 + tx * 8 + 4];
            unsigned long long bp[4] = { pk2(b0.x, b0.y), pk2(b0.z, b0.w), pk2(b1.x, b1.y), pk2(b1.z, b1.w) };
#pragma unroll
            for (int m = 0; m < 4; m++) {
                float av = X1[k * 128 + r4 + m];
                unsigned long long ad = pk2(av, av);
#pragma unroll
                for (int n = 0; n < 4; n++) acc[m][n] = ffma2(ad, bp[n], acc[m][n]);
            }
        }
#pragma unroll
        for (int m = 0; m < 4; m++)
#pragma unroll
            for (int n = 0; n < 4; n++) {
                float2 v = upk2(acc[m][n]);
                int i = r4 + m, j = tx * 8 + 2 * n;
                float2 kv = *(const float2*)&g_kuu2[p][Mm + i][Mm + j];
                float s0 = kv.x - v.x; if (i == j) s0 += JIT;
                float s1 = kv.y - v.y; if (i == j + 1) s1 += JIT;
                g_schur[p][i][j] = s0;
                g_schur[p][i][j + 1] = s1;
            }
    }
    __syncthreads();

    // reload transposed: X1 <- L_old^T, X2 <- u_tril^T (stride LDT=132)
    for (int e = t; e < Mm * Mm; e += 512) {
        int i = e >> 7, k = e & 127;
        X1[k * LDT + i] = L_old[(o * Mm + i) * Mm + k];
        X2[k * LDT + i] = (k <= i) ? u_tril_vec[o * 8256 + (i * (i + 1)) / 2 + k] : 0.0f;
    }
    __syncthreads();

    // cov TL[i][j] = sum_k X1t[k][i] X1t[k][j]
    {
        unsigned long long acc[4][4];
#pragma unroll
        for (int m = 0; m < 4; m++)
#pragma unroll
            for (int n = 0; n < 4; n++) acc[m][n] = 0ULL;
        for (int k = 0; k < Mm; k++) {
            float4 b0 = *(const float4*)&X1[k * LDT + tx * 8];
            float4 b1 = *(const float4*)&X1[k * LDT + tx * 8 + 4];
            unsigned long long bp[4] = { pk2(b0.x, b0.y), pk2(b0.z, b0.w), pk2(b1.x, b1.y), pk2(b1.z, b1.w) };
#pragma unroll
            for (int m = 0; m < 4; m++) {
                float av = X1[k * LDT + r4 + m];
                unsigned long long ad = pk2(av, av);
#pragma unroll
                for (int n = 0; n < 4; n++) acc[m][n] = ffma2(ad, bp[n], acc[m][n]);
            }
        }
#pragma unroll
        for (int m = 0; m < 4; m++)
#pragma unroll
            for (int n = 0; n < 4; n++) {
                float2 v = upk2(acc[m][n]);
                *(float2*)&g_cov[p][r4 + m][tx * 8 + 2 * n] = v;
            }
    }
    // cov BL[Mm+j][i] = sum_k G[k][j] * X1t[k][i]
    {
        unsigned long long acc[4][4];
#pragma unroll
        for (int m = 0; m < 4; m++)
#pragma unroll
            for (int n = 0; n < 4; n++) acc[m][n] = 0ULL;
        for (int k = 0; k < Mm; k++) {
            float4 b0 = *(const float4*)&X1[k * LDT + tx * 8];
            float4 b1 = *(const float4*)&X1[k * LDT + tx * 8 + 4];
            unsigned long long bp[4] = { pk2(b0.x, b0.y), pk2(b0.z, b0.w), pk2(b1.x, b1.y), pk2(b1.z, b1.w) };
#pragma unroll
            for (int m = 0; m < 4; m++) {
                float av = G[k * 128 + r4 + m];
                unsigned long long ad = pk2(av, av);
#pragma unroll
                for (int n = 0; n < 4; n++) acc[m][n] = ffma2(ad, bp[n], acc[m][n]);
            }
        }
#pragma unroll
        for (int m = 0; m < 4; m++)
#pragma unroll
            for (int n = 0; n < 4; n++) {
                float2 v = upk2(acc[m][n]);
                *(float2*)&g_cov[p][Mm + r4 + m][tx * 8 + 2 * n] = v;
            }
    }
    // cov BR[Mm+i][Mm+j] = sum_k X2t[k][i]X2t[k][j] + sum_k G[k][i]G[k][j]
    {
        unsigned long long acc[4][4];
#pragma unroll
        for (int m = 0; m < 4; m++)
#pragma unroll
            for (int n = 0; n < 4; n++) acc[m][n] = 0ULL;
        for (int k = 0; k < Mm; k++) {
            float4 b0 = *(const float4*)&X2[k * LDT + tx * 8];
            float4 b1 = *(const float4*)&X2[k * LDT + tx * 8 + 4];
            unsigned long long bp[4] = { pk2(b0.x, b0.y), pk2(b0.z, b0.w), pk2(b1.x, b1.y), pk2(b1.z, b1.w) };
            float4 c0 = *(const float4*)&G[k * 128 + tx * 8];
            float4 c1 = *(const float4*)&G[k * 128 + tx * 8 + 4];
            unsigned long long cp[4] = { pk2(c0.x, c0.y), pk2(c0.z, c0.w), pk2(c1.x, c1.y), pk2(c1.z, c1.w) };
#pragma unroll
            for (int m = 0; m < 4; m++) {
                float av = X2[k * LDT + r4 + m];
                float gv = G[k * 128 + r4 + m];
                unsigned long long ad = pk2(av, av);
                unsigned long long gd = pk2(gv, gv);
#pragma unroll
                for (int n = 0; n < 4; n++) {
                    acc[m][n] = ffma2(ad, bp[n], acc[m][n]);
                    acc[m][n] = ffma2(gd, cp[n], acc[m][n]);
                }
            }
        }
#pragma unroll
        for (int m = 0; m < 4; m++)
#pragma unroll
            for (int n = 0; n < 4; n++) {
                float2 v = upk2(acc[m][n]);
                *(float2*)&g_cov[p][Mm + r4 + m][Mm + tx * 8 + 2 * n] = v;
            }
    }
}

// ---------------- B1f (512 threads, FFMA2 phases) ----------------
// smem: S 16512 | T1 16896 | stgA 2048 | stgB 2048 | dinv 128 | mjs 256 = 37888 fl = 151552 B
__global__ __launch_bounds__(512, 1) void k_stageB1f() {
    extern __shared__ float sm[];
    float* S    = sm;            // stride 129
    float* T1   = sm + 16512;    // stride 132
    float* stgA = sm + 33408;
    float* stgB = sm + 35456;
    float* dinv = sm + 37504;
    float* mjs  = sm + 37632;
    int p = blockIdx.x, t = threadIdx.x;
    int tx = t & 15, ty = t >> 4;
    int r4 = ty * 4;

    for (int e = t; e < Mm * Mm; e += 512) {
        int i = e >> 7, j = e & 127;
        S[i * LDA + j] = g_schur[p][i][j];
    }
    if (t < 256) mjs[t] = g_mj[p][t];
    __syncthreads();
    chol128(S, dinv, t);
    trtri128_blocked(S, dinv, t);   // S = W22

    for (int e = t; e < Mm * Mm; e += 512) {
        int k = e >> 7, i = e & 127;
        g_Wt[p][Mm + k][Mm + i] = S[i * LDA + k];
    }

    // phase1: T1[c][j] = sum_i X1g[i][c] * W11g[i][j]
    {
        unsigned long long acc[4][4];
#pragma unroll
        for (int m = 0; m < 4; m++)
#pragma unroll
            for (int n = 0; n < 4; n++) acc[m][n] = 0ULL;
        for (int kc = 0; kc < Mm; kc += 16) {
            for (int e = t; e < 2048; e += 512) {
                int kk = e >> 7, q = e & 127;
                stgA[kk * 128 + q] = g_X1[p][kc + kk][q];
                stgB[kk * 128 + q] = g_W11[p][kc + kk][q];
            }
            __syncthreads();
#pragma unroll
            for (int kk = 0; kk < 16; kk++) {
                float4 b0 = *(const float4*)&stgB[kk * 128 + tx * 8];
                float4 b1 = *(const float4*)&stgB[kk * 128 + tx * 8 + 4];
                unsigned long long bp[4] = { pk2(b0.x, b0.y), pk2(b0.z, b0.w), pk2(b1.x, b1.y), pk2(b1.z, b1.w) };
#pragma unroll
                for (int m = 0; m < 4; m++) {
                    float av = stgA[kk * 128 + r4 + m];
                    unsigned long long ad = pk2(av, av);
#pragma unroll
                    for (int n = 0; n < 4; n++) acc[m][n] = ffma2(ad, bp[n], acc[m][n]);
                }
            }
            __syncthreads();
        }
#pragma unroll
        for (int m = 0; m < 4; m++)
#pragma unroll
            for (int n = 0; n < 4; n++) {
                float2 v = upk2(acc[m][n]);
                *(float2*)&T1[(r4 + m) * LDT + tx * 8 + 2 * n] = v;
            }
    }
    __syncthreads();

    // phase2: W21[r][j] = -sum_c W22[r][c] * T1[c][j]
    {
        unsigned long long acc[4][4];
#pragma unroll
        for (int m = 0; m < 4; m++)
#pragma unroll
            for (int n = 0; n < 4; n++) acc[m][n] = 0ULL;
        for (int c = 0; c < Mm; c++) {
            float4 b0 = *(const float4*)&T1[c * LDT + tx * 8];
            float4 b1 = *(const float4*)&T1[c * LDT + tx * 8 + 4];
            unsigned long long bp[4] = { pk2(b0.x, b0.y), pk2(b0.z, b0.w), pk2(b1.x, b1.y), pk2(b1.z, b1.w) };
#pragma unroll
            for (int m = 0; m < 4; m++) {
                float av = -S[(r4 + m) * LDA + c];
                unsigned long long ad = pk2(av, av);
#pragma unroll
                for (int n = 0; n < 4; n++) acc[m][n] = ffma2(ad, bp[n], acc[m][n]);
            }
        }
        __syncthreads();
#pragma unroll
        for (int m = 0; m < 4; m++)
#pragma unroll
            for (int n = 0; n < 4; n++) {
                float2 v = upk2(acc[m][n]);
                int r = r4 + m, j = tx * 8 + 2 * n;
                g_Wt[p][j][Mm + r] = v.x;
                g_Wt[p][j + 1][Mm + r] = v.y;
                T1[r * LDT + j] = v.x;
                T1[r * LDT + j + 1] = v.y;
            }
    }
    __syncthreads();

    if (t < 128) {
        float s = 0.0f;
        for (int j = 0; j < Mm; j++) s += T1[t * LDT + j] * mjs[j];
        for (int j = 0; j < Mm; j++) s += S[t * LDA + j] * mjs[Mm + j];
        g_vm[p][Mm + t] = s;
    }
}

// ---------------- B2n: block chol of cov+jit (unchanged) ----------------
__global__ __launch_bounds__(256, 1) void k_stageB2n() {
    extern __shared__ float sm[];
    float* C = sm;
    float* X = sm + 16512;
    float* dinv = sm + 33024;
    int p = blockIdx.x, t = threadIdx.x;
    int tx = t & 15, ty = t >> 4;

    for (int e = t; e < Mm * Mm; e += 256) {
        int i = e >> 7, j = e & 127;
        float v = g_cov[p][i][j];
        if (i == j) v += JIT;
        C[i * LDA + j] = v;
    }
    __syncthreads();
    chol128(C, dinv, t);
    for (int e = t; e < Mm * Mm; e += 256) {
        int i = e >> 7, k = e & 127;
        g_L11p[p][i][k] = (k <= i) ? C[i * LDA + k] : 0.0f;
    }
    for (int e = t; e < Mm * Mm; e += 256) {
        int r = e >> 7, j = e & 127;
        X[r * LDA + j] = g_cov[p][Mm + r][j];
    }
    __syncthreads();
    if (t < 128) {
        int r = t;
        for (int j = 0; j < Mm; j++) {
            float s0 = 0, s1 = 0, s2 = 0, s3 = 0;
            int k = 0;
            for (; k + 3 < j; k += 4) {
                s0 += X[r * LDA + k]     * C[j * LDA + k];
                s1 += X[r * LDA + k + 1] * C[j * LDA + k + 1];
                s2 += X[r * LDA + k + 2] * C[j * LDA + k + 2];
                s3 += X[r * LDA + k + 3] * C[j * LDA + k + 3];
            }
            for (; k < j; k++) s0 += X[r * LDA + k] * C[j * LDA + k];
            X[r * LDA + j] = (X[r * LDA + j] - ((s0 + s1) + (s2 + s3))) * dinv[j];
        }
    }
    __syncthreads();
    for (int e = t; e < Mm * Mm; e += 256) {
        int r = e >> 7, j = e & 127;
        g_L21p[p][r][j] = X[r * LDA + j];
    }
    {
        float c[8][8];
#pragma unroll
        for (int m = 0; m < 8; m++)
#pragma unroll
            for (int n = 0; n < 8; n++) c[m][n] = 0.0f;
        for (int k = 0; k < Mm; k++) {
            float a[8], b[8];
#pragma unroll
            for (int m = 0; m < 8; m++) a[m] = X[(ty + 16 * m) * LDA + k];
#pragma unroll
            for (int n = 0; n < 8; n++) b[n] = X[(tx + 16 * n) * LDA + k];
#pragma unroll
            for (int m = 0; m < 8; m++)
#pragma unroll
                for (int n = 0; n < 8; n++) c[m][n] += a[m] * b[n];
        }
        __syncthreads();
#pragma unroll
        for (int m = 0; m < 8; m++)
#pragma unroll
            for (int n = 0; n < 8; n++) {
                int i = ty + 16 * m, j = tx + 16 * n;
                float v = g_cov[p][Mm + i][Mm + j] - c[m][n];
                if (i == j) v += JIT;
                C[i * LDA + j] = v;
            }
    }
    __syncthreads();
    chol128(C, dinv, t);
    for (int e = t; e < Mm * Mm; e += 256) {
        int i = e >> 7, k = e & 127;
        g_L22p[p][i][k] = (k <= i) ? C[i * LDA + k] : 0.0f;
    }
}

// ---------------- k_R (FFMA2) ----------------
__global__ __launch_bounds__(256) void k_R() {
    __shared__ float As[16][128];
    __shared__ float Bs[16][128];
    int v = blockIdx.x, p = blockIdx.y;
    int t = threadIdx.x, tx = t & 15, ty = t >> 4;
    unsigned long long acc[8][4];
#pragma unroll
    for (int m = 0; m < 8; m++)
#pragma unroll
        for (int n = 0; n < 4; n++) acc[m][n] = 0ULL;

    int kTot = (v == 1) ? M2 : Mm;
    for (int kc = 0; kc < kTot; kc += 16) {
        for (int e = t; e < 2048; e += 256) {
            int kk = e >> 7, q = e & 127;
            int kg = kc + kk;
            float av, bv;
            if (v == 0) { av = g_Wt[p][kg][q];            bv = g_L11p[p][kg][q]; }
            else if (v == 1) {
                av = g_Wt[p][kg][Mm + q];
                bv = (kg < Mm) ? g_L11p[p][kg][q] : g_L21p[p][kg - Mm][q];
            }
            else { av = g_Wt[p][Mm + kg][Mm + q];         bv = g_L22p[p][kg][q]; }
            As[kk][q] = av;
            Bs[kk][q] = bv;
        }
        __syncthreads();
#pragma unroll
        for (int kk = 0; kk < 16; kk++) {
            float4 b0 = *(const float4*)&Bs[kk][tx * 8];
            float4 b1 = *(const float4*)&Bs[kk][tx * 8 + 4];
            unsigned long long bp[4] = { pk2(b0.x, b0.y), pk2(b0.z, b0.w), pk2(b1.x, b1.y), pk2(b1.z, b1.w) };
#pragma unroll
            for (int m = 0; m < 8; m++) {
                float av = As[kk][ty * 8 + m];
                unsigned long long ad = pk2(av, av);
#pragma unroll
                for (int n = 0; n < 4; n++) acc[m][n] = ffma2(ad, bp[n], acc[m][n]);
            }
        }
        __syncthreads();
    }
    int r0 = (v == 0) ? 0 : Mm;
    int c0 = (v == 2) ? Mm : 0;
#pragma unroll
    for (int m = 0; m < 8; m++) {
        float2 v0 = upk2(acc[m][0]), v1 = upk2(acc[m][1]), v2 = upk2(acc[m][2]), v3 = upk2(acc[m][3]);
        *(float4*)&g_R[p][r0 + ty * 8 + m][c0 + tx * 8]     = make_float4(v0.x, v0.y, v1.x, v1.y);
        *(float4*)&g_R[p][r0 + ty * 8 + m][c0 + tx * 8 + 4] = make_float4(v2.x, v2.y, v3.x, v3.y);
    }
}

// ---------------- gemmA: a = Linv @ kx (FFMA2) + d1/mu partials ----------------
__global__ __launch_bounds__(256) void k_gemmA() {
    __shared__ float As[16][128];
    __shared__ float Bs[16][128];
    __shared__ float vs[128];
    __shared__ float red[16][128];
    int p = blockIdx.z;
    int i0 = blockIdx.y * 128, b0 = blockIdx.x * 128;
    int t = threadIdx.x, tx = t % 16, ty = t / 16;
    if (t < 128) vs[t] = g_vm[p][i0 + t];
    unsigned long long acc[8][4];
#pragma unroll
    for (int m = 0; m < 8; m++)
#pragma unroll
        for (int n = 0; n < 4; n++) acc[m][n] = 0ULL;

    int kmax = i0 + 128;
    for (int kc = 0; kc < kmax; kc += 16) {
#pragma unroll
        for (int e = 0; e < 2; e++) {
            int q = t + e * 256;
            int kk = q >> 5, c4 = q & 31;
            *(float4*)&As[kk][c4 * 4] = *(const float4*)&g_Wt[p][kc + kk][i0 + c4 * 4];
            *(float4*)&Bs[kk][c4 * 4] = *(const float4*)&g_kx[p][kc + kk][b0 + c4 * 4];
        }
        __syncthreads();
#pragma unroll
        for (int kk = 0; kk < 16; kk++) {
            float4 a0 = *(const float4*)&As[kk][ty * 8];
            float4 a1 = *(const float4*)&As[kk][ty * 8 + 4];
            float4 q0 = *(const float4*)&Bs[kk][tx * 8];
            float4 q1 = *(const float4*)&Bs[kk][tx * 8 + 4];
            unsigned long long bp[4] = { pk2(q0.x, q0.y), pk2(q0.z, q0.w), pk2(q1.x, q1.y), pk2(q1.z, q1.w) };
            float am[8] = { a0.x, a0.y, a0.z, a0.w, a1.x, a1.y, a1.z, a1.w };
#pragma unroll
            for (int m = 0; m < 8; m++) {
                unsigned long long ad = pk2(am[m], am[m]);
#pragma unroll
                for (int n = 0; n < 4; n++) acc[m][n] = ffma2(ad, bp[n], acc[m][n]);
            }
        }
        __syncthreads();
    }
    float av[8][8];
#pragma unroll
    for (int m = 0; m < 8; m++) {
#pragma unroll
        for (int n = 0; n < 4; n++) {
            float2 v = upk2(acc[m][n]);
            av[m][n * 2] = v.x; av[m][n * 2 + 1] = v.y;
        }
        *(float4*)&g_a[p][i0 + ty * 8 + m][b0 + tx * 8]     = make_float4(av[m][0], av[m][1], av[m][2], av[m][3]);
        *(float4*)&g_a[p][i0 + ty * 8 + m][b0 + tx * 8 + 4] = make_float4(av[m][4], av[m][5], av[m][6], av[m][7]);
    }
#pragma unroll
    for (int n = 0; n < 8; n++) {
        float s = 0.0f;
#pragma unroll
        for (int m = 0; m < 8; m++) s += av[m][n] * av[m][n];
        red[ty][tx * 8 + n] = s;
    }
    __syncthreads();
    if (t < 128) {
        float s = 0.0f;
#pragma unroll
        for (int y = 0; y < 16; y++) s += red[y][t];
        g_d1p[blockIdx.y][p][b0 + t] = s;
    }
    __syncthreads();
#pragma unroll
    for (int n = 0; n < 8; n++) {
        float s = 0.0f;
#pragma unroll
        for (int m = 0; m < 8; m++) s += vs[ty * 8 + m] * av[m][n];
        red[ty][tx * 8 + n] = s;
    }
    __syncthreads();
    if (t < 128) {
        float s = 0.0f;
#pragma unroll
        for (int y = 0; y < 16; y++) s += red[y][t];
        g_mup[blockIdx.y][p][b0 + t] = s;
    }
}

// ---------------- gemmH: h = R^T @ a, d2 partials (FFMA2) ----------------
__global__ __launch_bounds__(256) void k_gemmH() {
    __shared__ float As[16][128];
    __shared__ float Bs[16][128];
    __shared__ float red[16][128];
    int p = blockIdx.z;
    int j0 = blockIdx.y * 128, b0 = blockIdx.x * 128;
    int t = threadIdx.x, tx = t % 16, ty = t / 16;
    unsigned long long acc[8][4];
#pragma unroll
    for (int m = 0; m < 8; m++)
#pragma unroll
        for (int n = 0; n < 4; n++) acc[m][n] = 0ULL;

    for (int kc = j0; kc < M2; kc += 16) {
#pragma unroll
        for (int e = 0; e < 2; e++) {
            int q = t + e * 256;
            int kk = q >> 5, c4 = q & 31;
            *(float4*)&As[kk][c4 * 4] = *(const float4*)&g_R[p][kc + kk][j0 + c4 * 4];
            *(float4*)&Bs[kk][c4 * 4] = *(const float4*)&g_a[p][kc + kk][b0 + c4 * 4];
        }
        __syncthreads();
#pragma unroll
        for (int kk = 0; kk < 16; kk++) {
            float4 a0 = *(const float4*)&As[kk][ty * 8];
            float4 a1 = *(const float4*)&As[kk][ty * 8 + 4];
            float4 q0 = *(const float4*)&Bs[kk][tx * 8];
            float4 q1 = *(const float4*)&Bs[kk][tx * 8 + 4];
            unsigned long long bp[4] = { pk2(q0.x, q0.y), pk2(q0.z, q0.w), pk2(q1.x, q1.y), pk2(q1.z, q1.w) };
            float am[8] = { a0.x, a0.y, a0.z, a0.w, a1.x, a1.y, a1.z, a1.w };
#pragma unroll
            for (int m = 0; m < 8; m++) {
                unsigned long long ad = pk2(am[m], am[m]);
#pragma unroll
                for (int n = 0; n < 4; n++) acc[m][n] = ffma2(ad, bp[n], acc[m][n]);
            }
        }
        __syncthreads();
    }
#pragma unroll
    for (int n = 0; n < 8; n++) {
        float s = 0.0f;
#pragma unroll
        for (int m = 0; m < 8; m++) {
            float2 v = upk2(acc[m][n / 2]);
            float h = (n & 1) ? v.y : v.x;
            s += h * h;
        }
        red[ty][tx * 8 + n] = s;
    }
    __syncthreads();
    if (t < 128) {
        float s = 0.0f;
#pragma unroll
        for (int y = 0; y < 16; y++) s += red[y][t];
        g_d2p[blockIdx.y][p][b0 + t] = s;
    }
}

// ---------------- final ----------------
__global__ void k_final(float* __restrict__ out) {
    int idx = blockIdx.x * 256 + threadIdx.x;
    if (idx >= HOB) return;
    int p = idx / Bb, b = idx % Bb;
    out[idx] = g_mup[0][p][b] + g_mup[1][p][b];
    out[HOB + idx] = g_sf2[p / Oo] - (g_d1p[0][p][b] + g_d1p[1][p][b]) + (g_d2p[0][p][b] + g_d2p[1][p][b]);
}

extern "C" void kernel_launch(void* const* d_in, const int* in_sizes, int n_in,
                              void* d_out, int out_size) {
    const float* x          = (const float*)d_in[0];
    const float* z          = (const float*)d_in[1];
    const float* u_mean     = (const float*)d_in[2];
    const float* u_tril_vec = (const float*)d_in[3];
    const float* m_old      = (const float*)d_in[4];
    const float* L_old      = (const float*)d_in[5];
    const float* z_old      = (const float*)d_in[6];
    const float* theta      = (const float*)d_in[7];
    float* out = (float*)d_out;

    static cudaStream_t s1 = 0;
    static cudaEvent_t evFork = 0, evKx = 0, evA = 0, evB1 = 0, evR = 0;
    if (!s1) {
        cudaStreamCreateWithFlags(&s1, cudaStreamNonBlocking);
        cudaEventCreateWithFlags(&evFork, cudaEventDisableTiming);
        cudaEventCreateWithFlags(&evKx,   cudaEventDisableTiming);
        cudaEventCreateWithFlags(&evA,    cudaEventDisableTiming);
        cudaEventCreateWithFlags(&evB1,   cudaEventDisableTiming);
        cudaEventCreateWithFlags(&evR,    cudaEventDisableTiming);
        cudaFuncSetAttribute(k_stageA,   cudaFuncAttributeMaxDynamicSharedMemorySize, 210944);
        cudaFuncSetAttribute(k_stageB1f, cudaFuncAttributeMaxDynamicSharedMemorySize, 151552);
        cudaFuncSetAttribute(k_stageB2n, cudaFuncAttributeMaxDynamicSharedMemorySize, 132608);
    }

    k_prep_theta<<<1, 128>>>(theta);
    k_prep_z<<<HO, 256>>>(z, z_old);
    cudaEventRecord(evFork, 0);
    k_kuu2<<<dim3(16, HO), 256>>>();
    k_stageA<<<HO, 512, 210944>>>(m_old, L_old, u_mean, u_tril_vec);
    cudaEventRecord(evA, 0);

    cudaStreamWaitEvent(s1, evFork, 0);
    k_prep_x<<<16, 256, 0, s1>>>(x);
    k_kx<<<dim3(8, HO), 256, 0, s1>>>();
    cudaEventRecord(evKx, s1);
    cudaStreamWaitEvent(s1, evA, 0);
    k_stageB2n<<<HO, 256, 132608, s1>>>();

    k_stageB1f<<<HO, 512, 151552>>>();
    cudaEventRecord(evB1, 0);

    cudaStreamWaitEvent(s1, evB1, 0);
    k_R<<<dim3(3, HO), 256, 0, s1>>>();
    cudaEventRecord(evR, s1);

    cudaStreamWaitEvent(0, evKx, 0);
    k_gemmA<<<dim3(8, 2, HO), 256>>>();
    cudaStreamWaitEvent(0, evR, 0);
    k_gemmH<<<dim3(8, 2, HO), 256>>>();
    k_final<<<512, 256>>>(out);
}

// round 10
// speedup vs baseline: 1.0559x; 1.0559x over previous
#include <cuda_runtime.h>

#define Hh 4
#define Oo 32
#define Mm 128
#define M2 256
#define Dd 16
#define Bb 1024
#define HO 128
#define HOB (HO*Bb)
#define JIT 1e-4f
#define LDA 129

// ---------------- f32x2 helpers ----------------
__device__ __forceinline__ unsigned long long pk2(float lo, float hi) {
    unsigned long long r;
    asm("mov.b64 %0, {%1, %2};" : "=l"(r) : "f"(lo), "f"(hi));
    return r;
}
__device__ __forceinline__ float2 upk2(unsigned long long v) {
    float2 r;
    asm("mov.b64 {%0, %1}, %2;" : "=f"(r.x), "=f"(r.y) : "l"(v));
    return r;
}
__device__ __forceinline__ unsigned long long ffma2(unsigned long long a, unsigned long long b, unsigned long long c) {
    unsigned long long d;
    asm("fma.rn.f32x2 %0, %1, %2, %3;" : "=l"(d) : "l"(a), "l"(b), "l"(c));
    return d;
}

// ---------------- device scratch ----------------
__device__ float g_sf2[Hh];
__device__ float g_invls[Hh][Dd];
__device__ float g_Xs[Hh][Bb][Dd];
__device__ float g_xn[Hh][Bb];
__device__ float g_Zs[HO][M2][Dd];
__device__ float g_zn[HO][M2];
__device__ float g_kuu2[HO][M2][M2];
__device__ float g_cov[HO][M2][M2];
__device__ float g_Wt[HO][M2][M2];     // Wt[k][i] = Linv256[i][k]
__device__ float g_R[HO][M2][M2];
__device__ float g_vm[HO][M2];
__device__ float g_mj[HO][M2];
__device__ float g_kx[HO][M2][Bb];
__device__ float g_a[HO][M2][Bb];
__device__ float g_X1[HO][Mm][Mm];
__device__ float g_W11[HO][Mm][Mm];
__device__ float g_AtX[HO][Mm][Mm];    // AtX[k][j]
__device__ float g_schur[HO][Mm][Mm];
__device__ float g_L11p[HO][Mm][Mm];
__device__ float g_L21p[HO][Mm][Mm];
__device__ float g_L22p[HO][Mm][Mm];
__device__ float g_d1p[2][HO][Bb];
__device__ float g_d2p[2][HO][Bb];
__device__ float g_mup[2][HO][Bb];

// ---------------- serial building blocks (dense 128, LD=129, blockDim-agnostic) ----------------
__device__ void chol128(float* Ls, float* dinv, int t) {
    for (int j = 0; j < Mm; j++) {
        if (t < 32) {
            float s = 0.0f;
            for (int k = t; k < j; k += 32) { float v = Ls[j * LDA + k]; s += v * v; }
            for (int w = 16; w; w >>= 1) s += __shfl_down_sync(0xffffffffu, s, w);
            if (t == 0) {
                float d = sqrtf(Ls[j * LDA + j] - s);
                Ls[j * LDA + j] = d;
                dinv[j] = 1.0f / d;
            }
        }
        __syncthreads();
        int i = j + 1 + t;
        if (i < Mm) {
            float s0 = 0, s1 = 0, s2 = 0, s3 = 0;
            int k = 0;
            for (; k + 3 < j; k += 4) {
                s0 += Ls[i * LDA + k]     * Ls[j * LDA + k];
                s1 += Ls[i * LDA + k + 1] * Ls[j * LDA + k + 1];
                s2 += Ls[i * LDA + k + 2] * Ls[j * LDA + k + 2];
                s3 += Ls[i * LDA + k + 3] * Ls[j * LDA + k + 3];
            }
            for (; k < j; k++) s0 += Ls[i * LDA + k] * Ls[j * LDA + k];
            Ls[i * LDA + j] = (Ls[i * LDA + j] - ((s0 + s1) + (s2 + s3))) * dinv[j];
        }
        __syncthreads();
    }
}

__device__ void trtri128_blocked(float* Ls, float* dinv, int t) {
    if (t == 0) Ls[0] = dinv[0];
    if (t == 1) Ls[64 * LDA + 64] = dinv[64];
    __syncthreads();
    for (int i = 1; i < 64; i++) {
        float v = 0.0f;
        bool actA = (t < i);
        int u = t - 128;
        bool actB = (u >= 0 && u < i);
        if (actA) {
            float s0 = 0, s1 = 0, s2 = 0, s3 = 0;
            int k = t;
            for (; k + 3 < i; k += 4) {
                s0 += Ls[i * LDA + k]     * Ls[(k)     * LDA + t];
                s1 += Ls[i * LDA + k + 1] * Ls[(k + 1) * LDA + t];
                s2 += Ls[i * LDA + k + 2] * Ls[(k + 2) * LDA + t];
                s3 += Ls[i * LDA + k + 3] * Ls[(k + 3) * LDA + t];
            }
            for (; k < i; k++) s0 += Ls[i * LDA + k] * Ls[k * LDA + t];
            v = -dinv[i] * ((s0 + s1) + (s2 + s3));
        } else if (actB) {
            const int O = 64 * LDA + 64;
            float s0 = 0, s1 = 0, s2 = 0, s3 = 0;
            int k = u;
            for (; k + 3 < i; k += 4) {
                s0 += Ls[O + i * LDA + k]     * Ls[O + (k)     * LDA + u];
                s1 += Ls[O + i * LDA + k + 1] * Ls[O + (k + 1) * LDA + u];
                s2 += Ls[O + i * LDA + k + 2] * Ls[O + (k + 2) * LDA + u];
                s3 += Ls[O + i * LDA + k + 3] * Ls[O + (k + 3) * LDA + u];
            }
            for (; k < i; k++) s0 += Ls[O + i * LDA + k] * Ls[O + k * LDA + u];
            v = -dinv[64 + i] * ((s0 + s1) + (s2 + s3));
        }
        __syncthreads();
        if (actA) Ls[i * LDA + t] = v;
        if (actB) Ls[(64 + i) * LDA + 64 + u] = v;
        if (t == 0) Ls[i * LDA + i] = dinv[i];
        if (t == 1) Ls[(64 + i) * LDA + 64 + i] = dinv[64 + i];
        __syncthreads();
    }
    for (int e = t; e < 64 * 64; e += blockDim.x) {
        int r = e >> 6, c = e & 63;
        if (c > r) { Ls[r * LDA + c] = 0.0f; Ls[(64 + r) * LDA + 64 + c] = 0.0f; }
        Ls[r * LDA + 64 + c] = 0.0f;
    }
    __syncthreads();
    int tx = t & 15, ty = (t >> 4) & 15;
    bool act = (t < 256);
    float T[4][4];
#pragma unroll
    for (int m = 0; m < 4; m++)
#pragma unroll
        for (int n = 0; n < 4; n++) T[m][n] = 0.0f;
    if (act) {
        for (int k = 0; k < 64; k++) {
            float a[4], b[4];
#pragma unroll
            for (int m = 0; m < 4; m++) a[m] = Ls[(64 + ty + 16 * m) * LDA + k];
#pragma unroll
            for (int n = 0; n < 4; n++) b[n] = Ls[k * LDA + tx + 16 * n];
#pragma unroll
            for (int m = 0; m < 4; m++)
#pragma unroll
                for (int n = 0; n < 4; n++) T[m][n] += a[m] * b[n];
        }
    }
    __syncthreads();
    if (act) {
#pragma unroll
        for (int m = 0; m < 4; m++)
#pragma unroll
            for (int n = 0; n < 4; n++) Ls[(64 + ty + 16 * m) * LDA + tx + 16 * n] = T[m][n];
    }
    __syncthreads();
#pragma unroll
    for (int m = 0; m < 4; m++)
#pragma unroll
        for (int n = 0; n < 4; n++) T[m][n] = 0.0f;
    if (act) {
        for (int k = 0; k < 64; k++) {
            float a[4], b[4];
#pragma unroll
            for (int m = 0; m < 4; m++) a[m] = Ls[(64 + ty + 16 * m) * LDA + 64 + k];
#pragma unroll
            for (int n = 0; n < 4; n++) b[n] = Ls[(64 + k) * LDA + tx + 16 * n];
#pragma unroll
            for (int m = 0; m < 4; m++)
#pragma unroll
                for (int n = 0; n < 4; n++) T[m][n] -= a[m] * b[n];
        }
    }
    __syncthreads();
    if (act) {
#pragma unroll
        for (int m = 0; m < 4; m++)
#pragma unroll
            for (int n = 0; n < 4; n++) Ls[(64 + ty + 16 * m) * LDA + tx + 16 * n] = T[m][n];
    }
    __syncthreads();
}

// ---------------- prep ----------------
__global__ void k_prep_theta(const float* __restrict__ theta) {
    int t = threadIdx.x;
    if (t < Hh * (Dd + 1)) {
        int h = t / (Dd + 1), c = t % (Dd + 1);
        float v = theta[t];
        if (c == 0) g_sf2[h] = expf(v);
        else        g_invls[h][c - 1] = expf(-v);
    }
}

__global__ void k_prep_x(const float* __restrict__ x) {
    int g = blockIdx.x * blockDim.x + threadIdx.x;
    if (g >= Hh * Bb) return;
    int h = g / Bb, b = g % Bb;
    float s = 0.0f;
#pragma unroll
    for (int d = 0; d < Dd; d++) {
        float v = x[b * Dd + d] * g_invls[h][d];
        g_Xs[h][b][d] = v;
        s += v * v;
    }
    g_xn[h][b] = s;
}

__global__ void k_prep_z(const float* __restrict__ z, const float* __restrict__ z_old) {
    int p = blockIdx.x;
    int h = p / Oo, o = p % Oo;
    int i = threadIdx.x;
    const float* src = (i < Mm) ? &z_old[(o * Mm + i) * Dd] : &z[(o * Mm + (i - Mm)) * Dd];
    float s = 0.0f;
#pragma unroll
    for (int d = 0; d < Dd; d++) {
        float v = src[d] * g_invls[h][d];
        g_Zs[p][i][d] = v;
        s += v * v;
    }
    g_zn[p][i] = s;
}

__global__ void k_kuu2() {
    __shared__ float zn[M2];
    int p = blockIdx.y, rc = blockIdx.x, t = threadIdx.x;
    float myz[Dd];
#pragma unroll
    for (int d = 0; d < Dd; d++) myz[d] = g_Zs[p][t][d];
    zn[t] = g_zn[p][t];
    __syncthreads();
    float sf2 = g_sf2[p / Oo];
#pragma unroll 2
    for (int e = 0; e < 16; e++) {
        int row = rc * 16 + e;
        float dot = 0.0f;
#pragma unroll
        for (int d = 0; d < Dd; d++) dot += g_Zs[p][row][d] * myz[d];
        float d2 = fmaxf(zn[row] + zn[t] - 2.0f * dot, 0.0f);
        g_kuu2[p][row][t] = sf2 * __expf(-0.5f * d2);
    }
}

__global__ void k_kx() {
    __shared__ float zs[M2][Dd + 1];
    __shared__ float zn[M2];
    int p = blockIdx.y, b0 = blockIdx.x * 128, t = threadIdx.x;
    int h = p / Oo;
    for (int e = t; e < M2 * Dd; e += 256) {
        int i = e >> 4, d = e & 15;
        zs[i][d] = g_Zs[p][i][d];
    }
    zn[t] = g_zn[p][t];
    __syncthreads();
    int bl = t & 127, half = t >> 7;
    float xr[Dd];
#pragma unroll
    for (int d = 0; d < Dd; d++) xr[d] = g_Xs[h][b0 + bl][d];
    float xnn = g_xn[h][b0 + bl];
    float sf2 = g_sf2[h];
    for (int ii = 0; ii < 128; ii++) {
        int i = half * 128 + ii;
        float dot = 0.0f;
#pragma unroll
        for (int d = 0; d < Dd; d++) dot += zs[i][d] * xr[d];
        float d2 = fmaxf(zn[i] + xnn - 2.0f * dot, 0.0f);
        g_kx[p][i][b0 + bl] = sf2 * __expf(-0.5f * d2);
    }
}

// ---------------- stage A (512 threads; cov split out) ----------------
// dyn smem: Ls 16512 | X1 16512 | X2 16512 | stg 2048 | dinv 128 | yv 128 | mbuf 128 = 51968 fl = 207872 B
__global__ __launch_bounds__(512, 1) void k_stageA(
        const float* __restrict__ m_old, const float* __restrict__ L_old,
        const float* __restrict__ u_mean, const float* __restrict__ u_tril_vec) {
    extern __shared__ float sm[];
    float* Ls   = sm;
    float* X1   = sm + 16512;
    float* X2   = sm + 33024;
    float* stg  = sm + 49536;
    float* dinv = sm + 51584;
    float* yv   = sm + 51712;
    float* mbuf = sm + 51840;
    int p = blockIdx.x, o = p % Oo, t = threadIdx.x;
    int tx = t & 15, ty = t >> 4;   // ty 0..31

    for (int e = t; e < Mm * Mm; e += 512) {
        int i = e >> 7, j = e & 127;
        float v = g_kuu2[p][i][j];
        if (i == j) v += JIT;
        Ls[i * LDA + j] = v;
    }
    __syncthreads();

    chol128(Ls, dinv, t);
    trtri128_blocked(Ls, dinv, t);   // Ls = W11 dense (upper zeros)

    for (int e = t; e < Mm * Mm; e += 512) {
        int i = e >> 7, k = e & 127;
        g_W11[p][i][k] = Ls[i * LDA + k];
        g_Wt[p][k][i]  = Ls[i * LDA + k];
    }

    // X1 = W11 @ kuf
    {
        float acc[4][8];
#pragma unroll
        for (int m = 0; m < 4; m++)
#pragma unroll
            for (int n = 0; n < 8; n++) acc[m][n] = 0.0f;
        for (int kc = 0; kc < Mm; kc += 16) {
            for (int e = t; e < 2048; e += 512) {
                int kk = e >> 7, c = e & 127;
                stg[kk * 128 + c] = g_kuu2[p][kc + kk][Mm + c];
            }
            __syncthreads();
#pragma unroll
            for (int kk = 0; kk < 16; kk++) {
                float a[4], b[8];
#pragma unroll
                for (int m = 0; m < 4; m++) a[m] = Ls[(ty + 32 * m) * LDA + kc + kk];
#pragma unroll
                for (int n = 0; n < 8; n++) b[n] = stg[kk * 128 + tx + 16 * n];
#pragma unroll
                for (int m = 0; m < 4; m++)
#pragma unroll
                    for (int n = 0; n < 8; n++) acc[m][n] += a[m] * b[n];
            }
            __syncthreads();
        }
#pragma unroll
        for (int m = 0; m < 4; m++)
#pragma unroll
            for (int n = 0; n < 8; n++) {
                X1[(ty + 32 * m) * LDA + tx + 16 * n] = acc[m][n];
                g_X1[p][ty + 32 * m][tx + 16 * n] = acc[m][n];
            }
    }
    // X2 = W11 @ L_old
    {
        float acc[4][8];
#pragma unroll
        for (int m = 0; m < 4; m++)
#pragma unroll
            for (int n = 0; n < 8; n++) acc[m][n] = 0.0f;
        for (int kc = 0; kc < Mm; kc += 16) {
            for (int e = t; e < 2048; e += 512) {
                int kk = e >> 7, c = e & 127;
                stg[kk * 128 + c] = L_old[(o * Mm + kc + kk) * Mm + c];
            }
            __syncthreads();
#pragma unroll
            for (int kk = 0; kk < 16; kk++) {
                float a[4], b[8];
#pragma unroll
                for (int m = 0; m < 4; m++) a[m] = Ls[(ty + 32 * m) * LDA + kc + kk];
#pragma unroll
                for (int n = 0; n < 8; n++) b[n] = stg[kk * 128 + tx + 16 * n];
#pragma unroll
                for (int m = 0; m < 4; m++)
#pragma unroll
                    for (int n = 0; n < 8; n++) acc[m][n] += a[m] * b[n];
            }
            __syncthreads();
        }
#pragma unroll
        for (int m = 0; m < 4; m++)
#pragma unroll
            for (int n = 0; n < 8; n++) X2[(ty + 32 * m) * LDA + tx + 16 * n] = acc[m][n];
    }
    __syncthreads();

    // yv = W11 @ m_old
    if (t < 128) mbuf[t] = m_old[o * Mm + t];
    __syncthreads();
    if (t < 128) {
        float s = 0.0f;
        for (int k = 0; k <= t; k++) s += Ls[t * LDA + k] * mbuf[k];
        yv[t] = s;
        g_vm[p][t] = s;
    }
    __syncthreads();

    // m_joint
    if (t < 128) {
        float s = 0.0f;
        for (int i = 0; i < Mm; i++) s += X1[i * LDA + t] * yv[i];
        g_mj[p][t] = mbuf[t];
        g_mj[p][Mm + t] = s + u_mean[o * Mm + t];
    }
    __syncthreads();

    // AtX[j][k] = sum_i X2[i][j]*X1[i][k] -> persist to g_AtX
    {
        float c[4][8];
#pragma unroll
        for (int m = 0; m < 4; m++)
#pragma unroll
            for (int n = 0; n < 8; n++) c[m][n] = 0.0f;
        for (int i = 0; i < Mm; i++) {
            float a[4], b[8];
#pragma unroll
            for (int m = 0; m < 4; m++) a[m] = X2[i * LDA + ty + 32 * m];
#pragma unroll
            for (int n = 0; n < 8; n++) b[n] = X1[i * LDA + tx + 16 * n];
#pragma unroll
            for (int m = 0; m < 4; m++)
#pragma unroll
                for (int n = 0; n < 8; n++) c[m][n] += a[m] * b[n];
        }
#pragma unroll
        for (int m = 0; m < 4; m++)
#pragma unroll
            for (int n = 0; n < 8; n++) g_AtX[p][ty + 32 * m][tx + 16 * n] = c[m][n];
    }

    // schur = kuu_new + jit I - X1^T X1
    {
        float c[4][8];
#pragma unroll
        for (int m = 0; m < 4; m++)
#pragma unroll
            for (int n = 0; n < 8; n++) c[m][n] = 0.0f;
        for (int k = 0; k < Mm; k++) {
            float a[4], b[8];
#pragma unroll
            for (int m = 0; m < 4; m++) a[m] = X1[k * LDA + ty + 32 * m];
#pragma unroll
            for (int n = 0; n < 8; n++) b[n] = X1[k * LDA + tx + 16 * n];
#pragma unroll
            for (int m = 0; m < 4; m++)
#pragma unroll
                for (int n = 0; n < 8; n++) c[m][n] += a[m] * b[n];
        }
#pragma unroll
        for (int m = 0; m < 4; m++)
#pragma unroll
            for (int n = 0; n < 8; n++) {
                int i = ty + 32 * m, j = tx + 16 * n;
                float v = g_kuu2[p][Mm + i][Mm + j] - c[m][n];
                if (i == j) v += JIT;
                g_schur[p][i][j] = v;
            }
    }
}

// ---------------- k_cov: cov_joint blocks from L_old / u_tril / AtX ----------------
// dyn smem: A1 16512 | A2 16512 = 33024 fl = 132096 B
__global__ __launch_bounds__(256, 1) void k_cov(const float* __restrict__ L_old,
                                                const float* __restrict__ u_tril_vec) {
    extern __shared__ float sm[];
    float* A1 = sm;          // L_old, then u_tril dense
    float* A2 = sm + 16512;  // AtX
    int p = blockIdx.x, o = p % Oo, t = threadIdx.x;
    int tx = t & 15, ty = t >> 4;

    for (int e = t; e < Mm * Mm; e += 256) {
        int i = e >> 7, j = e & 127;
        A1[i * LDA + j] = L_old[(o * Mm + i) * Mm + j];
        A2[i * LDA + j] = g_AtX[p][i][j];
    }
    __syncthreads();

    // cov TL[i][j] = sum_k L_old[i][k] L_old[j][k]
    {
        float c[8][8];
#pragma unroll
        for (int m = 0; m < 8; m++)
#pragma unroll
            for (int n = 0; n < 8; n++) c[m][n] = 0.0f;
        for (int k = 0; k < Mm; k++) {
            float a[8], b[8];
#pragma unroll
            for (int m = 0; m < 8; m++) a[m] = A1[(ty + 16 * m) * LDA + k];
#pragma unroll
            for (int n = 0; n < 8; n++) b[n] = A1[(tx + 16 * n) * LDA + k];
#pragma unroll
            for (int m = 0; m < 8; m++)
#pragma unroll
                for (int n = 0; n < 8; n++) c[m][n] += a[m] * b[n];
        }
#pragma unroll
        for (int m = 0; m < 8; m++)
#pragma unroll
            for (int n = 0; n < 8; n++) g_cov[p][ty + 16 * m][tx + 16 * n] = c[m][n];
    }
    // cov BL[Mm+j][i] = sum_k L_old[i][k] * AtX[k][j]
    {
        float c[8][8];
#pragma unroll
        for (int m = 0; m < 8; m++)
#pragma unroll
            for (int n = 0; n < 8; n++) c[m][n] = 0.0f;
        for (int k = 0; k < Mm; k++) {
            float a[8], b[8];
#pragma unroll
            for (int m = 0; m < 8; m++) a[m] = A2[k * LDA + ty + 16 * m];
#pragma unroll
            for (int n = 0; n < 8; n++) b[n] = A1[(tx + 16 * n) * LDA + k];
#pragma unroll
            for (int m = 0; m < 8; m++)
#pragma unroll
                for (int n = 0; n < 8; n++) c[m][n] += a[m] * b[n];
        }
#pragma unroll
        for (int m = 0; m < 8; m++)
#pragma unroll
            for (int n = 0; n < 8; n++) g_cov[p][Mm + ty + 16 * m][tx + 16 * n] = c[m][n];
    }
    __syncthreads();

    // reload A1 <- dense(u_tril)
    for (int e = t; e < Mm * Mm; e += 256) {
        int i = e >> 7, j = e & 127;
        A1[i * LDA + j] = (j <= i) ? u_tril_vec[o * 8256 + (i * (i + 1)) / 2 + j] : 0.0f;
    }
    __syncthreads();

    // cov BR[Mm+i][Mm+j] = sum_k U[i][k]U[j][k] + sum_k AtX[k][i]AtX[k][j]
    {
        float c[8][8];
#pragma unroll
        for (int m = 0; m < 8; m++)
#pragma unroll
            for (int n = 0; n < 8; n++) c[m][n] = 0.0f;
        for (int k = 0; k < Mm; k++) {
            float a[8], b[8];
#pragma unroll
            for (int m = 0; m < 8; m++) a[m] = A1[(ty + 16 * m) * LDA + k];
#pragma unroll
            for (int n = 0; n < 8; n++) b[n] = A1[(tx + 16 * n) * LDA + k];
#pragma unroll
            for (int m = 0; m < 8; m++)
#pragma unroll
                for (int n = 0; n < 8; n++) c[m][n] += a[m] * b[n];
        }
        for (int k = 0; k < Mm; k++) {
            float a[8], b[8];
#pragma unroll
            for (int m = 0; m < 8; m++) a[m] = A2[k * LDA + ty + 16 * m];
#pragma unroll
            for (int n = 0; n < 8; n++) b[n] = A2[k * LDA + tx + 16 * n];
#pragma unroll
            for (int m = 0; m < 8; m++)
#pragma unroll
                for (int n = 0; n < 8; n++) c[m][n] += a[m] * b[n];
        }
#pragma unroll
        for (int m = 0; m < 8; m++)
#pragma unroll
            for (int n = 0; n < 8; n++) g_cov[p][Mm + ty + 16 * m][Mm + tx + 16 * n] = c[m][n];
    }
}

// ---------------- B1f: chol(schur)+trtri -> W22; W21; Wt TR/BR; vm2 (fused) ----------------
// dyn smem: S 16512 | T1 16512 | stgA 2048 | stgB 2048 | dinv 128 | mjs 256 = 37504 fl = 150016 B
__global__ __launch_bounds__(256, 1) void k_stageB1f() {
    extern __shared__ float sm[];
    float* S    = sm;
    float* T1   = sm + 16512;
    float* stgA = sm + 33024;
    float* stgB = sm + 35072;
    float* dinv = sm + 37120;
    float* mjs  = sm + 37248;
    int p = blockIdx.x, t = threadIdx.x;
    int tx = t & 15, ty = t >> 4;

    for (int e = t; e < Mm * Mm; e += 256) {
        int i = e >> 7, j = e & 127;
        S[i * LDA + j] = g_schur[p][i][j];
    }
    mjs[t] = g_mj[p][t];
    __syncthreads();
    chol128(S, dinv, t);
    trtri128_blocked(S, dinv, t);   // S = W22

    for (int e = t; e < Mm * Mm; e += 256) {
        int k = e >> 7, i = e & 127;
        g_Wt[p][Mm + k][Mm + i] = S[i * LDA + k];
    }

    // phase1: T1[c][j] = sum_i X1[i][c] * W11[i][j]
    {
        float acc[8][8];
#pragma unroll
        for (int m = 0; m < 8; m++)
#pragma unroll
            for (int n = 0; n < 8; n++) acc[m][n] = 0.0f;
        for (int kc = 0; kc < Mm; kc += 16) {
            for (int e = t; e < 2048; e += 256) {
                int kk = e >> 7, q = e & 127;
                stgA[kk * 128 + q] = g_X1[p][kc + kk][q];
                stgB[kk * 128 + q] = g_W11[p][kc + kk][q];
            }
            __syncthreads();
#pragma unroll
            for (int kk = 0; kk < 16; kk++) {
                float a[8], b[8];
#pragma unroll
                for (int m = 0; m < 8; m++) a[m] = stgA[kk * 128 + ty + 16 * m];
#pragma unroll
                for (int n = 0; n < 8; n++) b[n] = stgB[kk * 128 + tx + 16 * n];
#pragma unroll
                for (int m = 0; m < 8; m++)
#pragma unroll
                    for (int n = 0; n < 8; n++) acc[m][n] += a[m] * b[n];
            }
            __syncthreads();
        }
#pragma unroll
        for (int m = 0; m < 8; m++)
#pragma unroll
            for (int n = 0; n < 8; n++) T1[(ty + 16 * m) * LDA + tx + 16 * n] = acc[m][n];
    }
    __syncthreads();

    // phase2: W21[r][j] = -sum_c W22[r][c] * T1[c][j]
    {
        float acc[8][8];
#pragma unroll
        for (int m = 0; m < 8; m++)
#pragma unroll
            for (int n = 0; n < 8; n++) acc[m][n] = 0.0f;
        for (int c = 0; c < Mm; c++) {
            float a[8], b[8];
#pragma unroll
            for (int m = 0; m < 8; m++) a[m] = S[(ty + 16 * m) * LDA + c];
#pragma unroll
            for (int n = 0; n < 8; n++) b[n] = T1[c * LDA + tx + 16 * n];
#pragma unroll
            for (int m = 0; m < 8; m++)
#pragma unroll
                for (int n = 0; n < 8; n++) acc[m][n] -= a[m] * b[n];
        }
        __syncthreads();
#pragma unroll
        for (int m = 0; m < 8; m++)
#pragma unroll
            for (int n = 0; n < 8; n++) {
                int r = ty + 16 * m, j = tx + 16 * n;
                g_Wt[p][j][Mm + r] = acc[m][n];
                T1[r * LDA + j] = acc[m][n];
            }
    }
    __syncthreads();

    if (t < 128) {
        float s = 0.0f;
        for (int j = 0; j < Mm; j++) s += T1[t * LDA + j] * mjs[j];
        for (int j = 0; j < Mm; j++) s += S[t * LDA + j] * mjs[Mm + j];
        g_vm[p][Mm + t] = s;
    }
}

// ---------------- B2n: block chol of cov+jit -> L11p, L21p, L22p ----------------
__global__ __launch_bounds__(256, 1) void k_stageB2n() {
    extern __shared__ float sm[];
    float* C = sm;
    float* X = sm + 16512;
    float* dinv = sm + 33024;
    int p = blockIdx.x, t = threadIdx.x;
    int tx = t & 15, ty = t >> 4;

    for (int e = t; e < Mm * Mm; e += 256) {
        int i = e >> 7, j = e & 127;
        float v = g_cov[p][i][j];
        if (i == j) v += JIT;
        C[i * LDA + j] = v;
    }
    __syncthreads();
    chol128(C, dinv, t);
    for (int e = t; e < Mm * Mm; e += 256) {
        int i = e >> 7, k = e & 127;
        g_L11p[p][i][k] = (k <= i) ? C[i * LDA + k] : 0.0f;
    }
    for (int e = t; e < Mm * Mm; e += 256) {
        int r = e >> 7, j = e & 127;
        X[r * LDA + j] = g_cov[p][Mm + r][j];
    }
    __syncthreads();
    if (t < 128) {
        int r = t;
        for (int j = 0; j < Mm; j++) {
            float s0 = 0, s1 = 0, s2 = 0, s3 = 0;
            int k = 0;
            for (; k + 3 < j; k += 4) {
                s0 += X[r * LDA + k]     * C[j * LDA + k];
                s1 += X[r * LDA + k + 1] * C[j * LDA + k + 1];
                s2 += X[r * LDA + k + 2] * C[j * LDA + k + 2];
                s3 += X[r * LDA + k + 3] * C[j * LDA + k + 3];
            }
            for (; k < j; k++) s0 += X[r * LDA + k] * C[j * LDA + k];
            X[r * LDA + j] = (X[r * LDA + j] - ((s0 + s1) + (s2 + s3))) * dinv[j];
        }
    }
    __syncthreads();
    for (int e = t; e < Mm * Mm; e += 256) {
        int r = e >> 7, j = e & 127;
        g_L21p[p][r][j] = X[r * LDA + j];
    }
    {
        float c[8][8];
#pragma unroll
        for (int m = 0; m < 8; m++)
#pragma unroll
            for (int n = 0; n < 8; n++) c[m][n] = 0.0f;
        for (int k = 0; k < Mm; k++) {
            float a[8], b[8];
#pragma unroll
            for (int m = 0; m < 8; m++) a[m] = X[(ty + 16 * m) * LDA + k];
#pragma unroll
            for (int n = 0; n < 8; n++) b[n] = X[(tx + 16 * n) * LDA + k];
#pragma unroll
            for (int m = 0; m < 8; m++)
#pragma unroll
                for (int n = 0; n < 8; n++) c[m][n] += a[m] * b[n];
        }
        __syncthreads();
#pragma unroll
        for (int m = 0; m < 8; m++)
#pragma unroll
            for (int n = 0; n < 8; n++) {
                int i = ty + 16 * m, j = tx + 16 * n;
                float v = g_cov[p][Mm + i][Mm + j] - c[m][n];
                if (i == j) v += JIT;
                C[i * LDA + j] = v;
            }
    }
    __syncthreads();
    chol128(C, dinv, t);
    for (int e = t; e < Mm * Mm; e += 256) {
        int i = e >> 7, k = e & 127;
        g_L22p[p][i][k] = (k <= i) ? C[i * LDA + k] : 0.0f;
    }
}

// ---------------- k_R: R blocks. grid (3, HO) ----------------
__global__ __launch_bounds__(256) void k_R() {
    __shared__ float As[16][128];
    __shared__ float Bs[16][128];
    int v = blockIdx.x, p = blockIdx.y;
    int t = threadIdx.x, tx = t & 15, ty = t >> 4;
    float acc[8][8];
#pragma unroll
    for (int m = 0; m < 8; m++)
#pragma unroll
        for (int n = 0; n < 8; n++) acc[m][n] = 0.0f;

    int kTot = (v == 1) ? M2 : Mm;
    for (int kc = 0; kc < kTot; kc += 16) {
        for (int e = t; e < 2048; e += 256) {
            int kk = e >> 7, q = e & 127;
            int kg = kc + kk;
            float av, bv;
            if (v == 0) { av = g_Wt[p][kg][q];            bv = g_L11p[p][kg][q]; }
            else if (v == 1) {
                av = g_Wt[p][kg][Mm + q];
                bv = (kg < Mm) ? g_L11p[p][kg][q] : g_L21p[p][kg - Mm][q];
            }
            else { av = g_Wt[p][Mm + kg][Mm + q];         bv = g_L22p[p][kg][q]; }
            As[kk][q] = av;
            Bs[kk][q] = bv;
        }
        __syncthreads();
#pragma unroll
        for (int kk = 0; kk < 16; kk++) {
            float4 a0 = *(const float4*)&As[kk][ty * 8];
            float4 a1 = *(const float4*)&As[kk][ty * 8 + 4];
            float4 b0 = *(const float4*)&Bs[kk][tx * 8];
            float4 b1 = *(const float4*)&Bs[kk][tx * 8 + 4];
            float am[8] = { a0.x, a0.y, a0.z, a0.w, a1.x, a1.y, a1.z, a1.w };
            float bn[8] = { b0.x, b0.y, b0.z, b0.w, b1.x, b1.y, b1.z, b1.w };
#pragma unroll
            for (int m = 0; m < 8; m++)
#pragma unroll
                for (int n = 0; n < 8; n++) acc[m][n] += am[m] * bn[n];
        }
        __syncthreads();
    }
    int r0 = (v == 0) ? 0 : Mm;
    int c0 = (v == 2) ? Mm : 0;
#pragma unroll
    for (int m = 0; m < 8; m++) {
        *(float4*)&g_R[p][r0 + ty * 8 + m][c0 + tx * 8]     = make_float4(acc[m][0], acc[m][1], acc[m][2], acc[m][3]);
        *(float4*)&g_R[p][r0 + ty * 8 + m][c0 + tx * 8 + 4] = make_float4(acc[m][4], acc[m][5], acc[m][6], acc[m][7]);
    }
}

// ---------------- gemmA: a = Linv @ kx (FFMA2) + d1/mu partials ----------------
__global__ __launch_bounds__(256) void k_gemmA() {
    __shared__ float As[16][128];
    __shared__ float Bs[16][128];
    __shared__ float vs[128];
    __shared__ float red[16][128];
    int p = blockIdx.z;
    int i0 = blockIdx.y * 128, b0 = blockIdx.x * 128;
    int t = threadIdx.x, tx = t % 16, ty = t / 16;
    if (t < 128) vs[t] = g_vm[p][i0 + t];
    unsigned long long acc[8][4];
#pragma unroll
    for (int m = 0; m < 8; m++)
#pragma unroll
        for (int n = 0; n < 4; n++) acc[m][n] = 0ULL;

    int kmax = i0 + 128;
    for (int kc = 0; kc < kmax; kc += 16) {
#pragma unroll
        for (int e = 0; e < 2; e++) {
            int q = t + e * 256;
            int kk = q >> 5, c4 = q & 31;
            *(float4*)&As[kk][c4 * 4] = *(const float4*)&g_Wt[p][kc + kk][i0 + c4 * 4];
            *(float4*)&Bs[kk][c4 * 4] = *(const float4*)&g_kx[p][kc + kk][b0 + c4 * 4];
        }
        __syncthreads();
#pragma unroll
        for (int kk = 0; kk < 16; kk++) {
            float4 a0 = *(const float4*)&As[kk][ty * 8];
            float4 a1 = *(const float4*)&As[kk][ty * 8 + 4];
            float4 q0 = *(const float4*)&Bs[kk][tx * 8];
            float4 q1 = *(const float4*)&Bs[kk][tx * 8 + 4];
            unsigned long long bp[4] = { pk2(q0.x, q0.y), pk2(q0.z, q0.w), pk2(q1.x, q1.y), pk2(q1.z, q1.w) };
            float am[8] = { a0.x, a0.y, a0.z, a0.w, a1.x, a1.y, a1.z, a1.w };
#pragma unroll
            for (int m = 0; m < 8; m++) {
                unsigned long long ad = pk2(am[m], am[m]);
#pragma unroll
                for (int n = 0; n < 4; n++) acc[m][n] = ffma2(ad, bp[n], acc[m][n]);
            }
        }
        __syncthreads();
    }
    float av[8][8];
#pragma unroll
    for (int m = 0; m < 8; m++) {
#pragma unroll
        for (int n = 0; n < 4; n++) {
            float2 v = upk2(acc[m][n]);
            av[m][n * 2] = v.x; av[m][n * 2 + 1] = v.y;
        }
        *(float4*)&g_a[p][i0 + ty * 8 + m][b0 + tx * 8]     = make_float4(av[m][0], av[m][1], av[m][2], av[m][3]);
        *(float4*)&g_a[p][i0 + ty * 8 + m][b0 + tx * 8 + 4] = make_float4(av[m][4], av[m][5], av[m][6], av[m][7]);
    }
#pragma unroll
    for (int n = 0; n < 8; n++) {
        float s = 0.0f;
#pragma unroll
        for (int m = 0; m < 8; m++) s += av[m][n] * av[m][n];
        red[ty][tx * 8 + n] = s;
    }
    __syncthreads();
    if (t < 128) {
        float s = 0.0f;
#pragma unroll
        for (int y = 0; y < 16; y++) s += red[y][t];
        g_d1p[blockIdx.y][p][b0 + t] = s;
    }
    __syncthreads();
#pragma unroll
    for (int n = 0; n < 8; n++) {
        float s = 0.0f;
#pragma unroll
        for (int m = 0; m < 8; m++) s += vs[ty * 8 + m] * av[m][n];
        red[ty][tx * 8 + n] = s;
    }
    __syncthreads();
    if (t < 128) {
        float s = 0.0f;
#pragma unroll
        for (int y = 0; y < 16; y++) s += red[y][t];
        g_mup[blockIdx.y][p][b0 + t] = s;
    }
}

// ---------------- gemmH: h = R^T @ a, d2 partials (FFMA2) ----------------
__global__ __launch_bounds__(256) void k_gemmH() {
    __shared__ float As[16][128];
    __shared__ float Bs[16][128];
    __shared__ float red[16][128];
    int p = blockIdx.z;
    int j0 = blockIdx.y * 128, b0 = blockIdx.x * 128;
    int t = threadIdx.x, tx = t % 16, ty = t / 16;
    unsigned long long acc[8][4];
#pragma unroll
    for (int m = 0; m < 8; m++)
#pragma unroll
        for (int n = 0; n < 4; n++) acc[m][n] = 0ULL;

    for (int kc = j0; kc < M2; kc += 16) {
#pragma unroll
        for (int e = 0; e < 2; e++) {
            int q = t + e * 256;
            int kk = q >> 5, c4 = q & 31;
            *(float4*)&As[kk][c4 * 4] = *(const float4*)&g_R[p][kc + kk][j0 + c4 * 4];
            *(float4*)&Bs[kk][c4 * 4] = *(const float4*)&g_a[p][kc + kk][b0 + c4 * 4];
        }
        __syncthreads();
#pragma unroll
        for (int kk = 0; kk < 16; kk++) {
            float4 a0 = *(const float4*)&As[kk][ty * 8];
            float4 a1 = *(const float4*)&As[kk][ty * 8 + 4];
            float4 q0 = *(const float4*)&Bs[kk][tx * 8];
            float4 q1 = *(const float4*)&Bs[kk][tx * 8 + 4];
            unsigned long long bp[4] = { pk2(q0.x, q0.y), pk2(q0.z, q0.w), pk2(q1.x, q1.y), pk2(q1.z, q1.w) };
            float am[8] = { a0.x, a0.y, a0.z, a0.w, a1.x, a1.y, a1.z, a1.w };
#pragma unroll
            for (int m = 0; m < 8; m++) {
                unsigned long long ad = pk2(am[m], am[m]);
#pragma unroll
                for (int n = 0; n < 4; n++) acc[m][n] = ffma2(ad, bp[n], acc[m][n]);
            }
        }
        __syncthreads();
    }
#pragma unroll
    for (int n = 0; n < 8; n++) {
        float s = 0.0f;
#pragma unroll
        for (int m = 0; m < 8; m++) {
            float2 v = upk2(acc[m][n / 2]);
            float h = (n & 1) ? v.y : v.x;
            s += h * h;
        }
        red[ty][tx * 8 + n] = s;
    }
    __syncthreads();
    if (t < 128) {
        float s = 0.0f;
#pragma unroll
        for (int y = 0; y < 16; y++) s += red[y][t];
        g_d2p[blockIdx.y][p][b0 + t] = s;
    }
}

// ---------------- final ----------------
__global__ void k_final(float* __restrict__ out) {
    int idx = blockIdx.x * 256 + threadIdx.x;
    if (idx >= HOB) return;
    int p = idx / Bb, b = idx % Bb;
    out[idx] = g_mup[0][p][b] + g_mup[1][p][b];
    out[HOB + idx] = g_sf2[p / Oo] - (g_d1p[0][p][b] + g_d1p[1][p][b]) + (g_d2p[0][p][b] + g_d2p[1][p][b]);
}

extern "C" void kernel_launch(void* const* d_in, const int* in_sizes, int n_in,
                              void* d_out, int out_size) {
    const float* x          = (const float*)d_in[0];
    const float* z          = (const float*)d_in[1];
    const float* u_mean     = (const float*)d_in[2];
    const float* u_tril_vec = (const float*)d_in[3];
    const float* m_old      = (const float*)d_in[4];
    const float* L_old      = (const float*)d_in[5];
    const float* z_old      = (const float*)d_in[6];
    const float* theta      = (const float*)d_in[7];
    float* out = (float*)d_out;

    static cudaStream_t s1 = 0;
    static cudaEvent_t evFork = 0, evKx = 0, evA = 0, evB1 = 0, evR = 0;
    if (!s1) {
        cudaStreamCreateWithFlags(&s1, cudaStreamNonBlocking);
        cudaEventCreateWithFlags(&evFork, cudaEventDisableTiming);
        cudaEventCreateWithFlags(&evKx,   cudaEventDisableTiming);
        cudaEventCreateWithFlags(&evA,    cudaEventDisableTiming);
        cudaEventCreateWithFlags(&evB1,   cudaEventDisableTiming);
        cudaEventCreateWithFlags(&evR,    cudaEventDisableTiming);
        cudaFuncSetAttribute(k_stageA,   cudaFuncAttributeMaxDynamicSharedMemorySize, 207872);
        cudaFuncSetAttribute(k_cov,      cudaFuncAttributeMaxDynamicSharedMemorySize, 132096);
        cudaFuncSetAttribute(k_stageB1f, cudaFuncAttributeMaxDynamicSharedMemorySize, 150016);
        cudaFuncSetAttribute(k_stageB2n, cudaFuncAttributeMaxDynamicSharedMemorySize, 132608);
    }

    // s0 chain (stageA stays at host-launch slot 3 for the profiler)
    k_prep_theta<<<1, 128>>>(theta);
    k_prep_z<<<HO, 256>>>(z, z_old);
    cudaEventRecord(evFork, 0);
    k_kuu2<<<dim3(16, HO), 256>>>();
    k_stageA<<<HO, 512, 207872>>>(m_old, L_old, u_mean, u_tril_vec);
    cudaEventRecord(evA, 0);

    // s1: prep_x + kx overlap stageA; then cov + B2n overlap B1f
    cudaStreamWaitEvent(s1, evFork, 0);
    k_prep_x<<<16, 256, 0, s1>>>(x);
    k_kx<<<dim3(8, HO), 256, 0, s1>>>();
    cudaEventRecord(evKx, s1);
    cudaStreamWaitEvent(s1, evA, 0);
    k_cov<<<HO, 256, 132096, s1>>>(L_old, u_tril_vec);
    k_stageB2n<<<HO, 256, 132608, s1>>>();

    // s0: B1f
    k_stageB1f<<<HO, 256, 150016>>>();
    cudaEventRecord(evB1, 0);

    // s1: k_R (needs B2n + B1f), overlaps gemmA
    cudaStreamWaitEvent(s1, evB1, 0);
    k_R<<<dim3(3, HO), 256, 0, s1>>>();
    cudaEventRecord(evR, s1);

    // s0: gemmA (needs B1f + kx), gemmH (needs R + a), final
    cudaStreamWaitEvent(0, evKx, 0);
    k_gemmA<<<dim3(8, 2, HO), 256>>>();
    cudaStreamWaitEvent(0, evR, 0);
    k_gemmH<<<dim3(8, 2, HO), 256>>>();
    k_final<<<512, 256>>>(out);
}